// round 6
// baseline (speedup 1.0000x reference)
#include <cuda_runtime.h>
#include <cuda_bf16.h>

// Weighted AUC, single fused kernel, dual-pipe atomics.
// label==1: tp add -> SMEM private hist (L1 ATOMS pipe)
// label==0: fp add -> GLOBAL per-task hist (L2 REDG pipe, L2-resident)
// area = sum_b fp[b]*(TP_above(b)+0.5*tp[b]); auc = area/(TP_tot*FP_tot).
// Last block per task finalizes and restores zero-state for graph replay.

#define T_TASKS 16
#define NB 4096                // prediction bins, uniform [0,1)
#define NPT 2097152
#define N4 (NPT / 4)           // 524288 float4 per task
#define CHUNKS 37              // 16*37 = 592 blocks = 4 per SM on 148 SMs
#define PER_CHUNK 14171        // ceil(N4/37)
#define THREADS 512
#define BINS_PT (NB / THREADS) // 8 bins per thread in finalize

__device__ float        g_hist[T_TASKS * 2 * NB];   // [tp NB][fp NB] per task, zero-init
__device__ unsigned int g_count[T_TASKS];           // zero-init

__global__ void __launch_bounds__(THREADS, 4) auc_kernel(
    const float4* __restrict__ pp, const float4* __restrict__ ll,
    const float4* __restrict__ ww, float* __restrict__ out)
{
    __shared__ __align__(16) float sh[NB];   // 16 KB: tp hist only
    const int task = blockIdx.y;
    const int t    = threadIdx.x;

    for (int i = t; i < NB; i += THREADS) sh[i] = 0.0f;
    __syncthreads();

    float* gh   = g_hist + task * 2 * NB;   // tp half
    float* g_fp = gh + NB;                  // fp half (L2-resident atomics)

    // ---- histogram phase ----
    {
        const int start = blockIdx.x * PER_CHUNK;
        const int end   = (start + PER_CHUNK < N4) ? start + PER_CHUNK : N4;
        const int base  = task * N4 + start;
        const int cnt   = end - start;

#pragma unroll 2
        for (int i = t; i < cnt; i += THREADS) {
            float4 pv = __ldcs(pp + base + i);
            float4 lv = __ldcs(ll + base + i);
            float4 wv = __ldcs(ww + base + i);
#define DO_COMP(c)                                                        \
            {                                                             \
                int b = (int)(pv.c * (float)NB);                          \
                b = b > NB - 1 ? NB - 1 : b;                              \
                if (lv.c != 0.0f) atomicAdd(sh + b, wv.c);                \
                else              atomicAdd(g_fp + b, wv.c);              \
            }
            DO_COMP(x) DO_COMP(y) DO_COMP(z) DO_COMP(w)
#undef DO_COMP
        }
    }
    __syncthreads();

    // ---- flush tp half to global ----
    for (int i = t; i < NB; i += THREADS) {
        float v = sh[i];
        if (v != 0.0f) atomicAdd(gh + i, v);
    }
    __threadfence();
    __syncthreads();

    // ---- elect last block per task ----
    __shared__ unsigned s_last;
    if (t == 0) s_last = atomicAdd(&g_count[task], 1u);
    __syncthreads();
    if (s_last != CHUNKS - 1) return;
    __threadfence();   // acquire: see all blocks' tp flushes and fp REDGs

    // ---- finalize: suffix scan of tp + bilinear area + auc ----
    float* fsum = sh;                 // reuse smem (512 floats)
    float  th[BINS_PT], loc[BINS_PT];
    float  s = 0.0f;
#pragma unroll
    for (int j = BINS_PT - 1; j >= 0; --j) {
        th[j] = gh[t * BINS_PT + j];
        s += th[j];
        loc[j] = s;                   // inclusive suffix within thread's bins
    }
    __syncthreads();
    fsum[t] = s;
    __syncthreads();

    // Hillis-Steele inclusive suffix scan over 512 thread totals
    for (int off = 1; off < THREADS; off <<= 1) {
        float v = (t + off < THREADS) ? fsum[t + off] : 0.0f;
        __syncthreads();
        fsum[t] += v;
        __syncthreads();
    }
    const float above    = (t + 1 < THREADS) ? fsum[t + 1] : 0.0f;
    const float tp_total = fsum[0];
    __syncthreads();

    double a = 0.0, f = 0.0;
#pragma unroll
    for (int j = 0; j < BINS_PT; ++j) {
        float fv  = g_fp[t * BINS_PT + j];
        float lut = above + loc[j] - 0.5f * th[j];
        a += (double)fv * (double)lut;
        f += (double)fv;
    }

#pragma unroll
    for (int off = 16; off; off >>= 1) {
        a += __shfl_down_sync(0xffffffffu, a, off);
        f += __shfl_down_sync(0xffffffffu, f, off);
    }
    double* sred = (double*)sh;       // reuse smem (32 doubles)
    const int warp = t >> 5, lane = t & 31;
    __syncthreads();
    if (lane == 0) { sred[warp] = a; sred[16 + warp] = f; }
    __syncthreads();

    if (t == 0) {
        double ta = 0.0, tf = 0.0;
#pragma unroll
        for (int k = 0; k < THREADS / 32; ++k) { ta += sred[k]; tf += sred[16 + k]; }
        double denom = tf * (double)tp_total;
        out[task] = (denom == 0.0) ? 0.5f : (float)(ta / denom);
        g_count[task] = 0u;           // restore invariant
    }

    // restore g_hist zeros (both halves) for next call / replay
    for (int i = t; i < 2 * NB; i += THREADS) gh[i] = 0.0f;
}

extern "C" void kernel_launch(void* const* d_in, const int* in_sizes, int n_in,
                              void* d_out, int out_size) {
    int off = (n_in >= 4 && in_sizes[0] == 1) ? 1 : 0;
    const float4* p = (const float4*)d_in[off + 0];
    const float4* l = (const float4*)d_in[off + 1];
    const float4* w = (const float4*)d_in[off + 2];

    dim3 g(CHUNKS, T_TASKS);
    auc_kernel<<<g, THREADS>>>(p, l, w, (float*)d_out);
}

// round 7
// speedup vs baseline: 2.3931x; 2.3931x over previous
#include <cuda_runtime.h>
#include <cuda_bf16.h>

// Weighted AUC, single fused kernel (R5 structure + software-pipelined loads).
// Labels are exactly 0/1: each element adds w to smem tp_hist[bin] or fp_hist[bin]
// (one ATOMS, offset-selected). area = sum_b fp[b]*(TP_above(b)+0.5*tp[b]);
// auc = area/(TP_tot*FP_tot). Last block per task finalizes in-kernel and
// restores zeroed global state so every graph replay is identical.

#define T_TASKS 16
#define NB 4096                // prediction bins, uniform [0,1)
#define NPT 2097152
#define N4 (NPT / 4)           // 524288 float4 per task
#define CHUNKS 37              // 16*37 = 592 blocks = 4 per SM on 148 SMs
#define PER_CHUNK 14171        // ceil(N4/37)
#define THREADS 512
#define BINS_PT (NB / THREADS) // 8 bins per thread in finalize

__device__ float        g_hist[T_TASKS * 2 * NB];   // [tp NB][fp NB] per task, zero-init
__device__ unsigned int g_count[T_TASKS];           // zero-init

__global__ void __launch_bounds__(THREADS, 4) auc_kernel(
    const float4* __restrict__ pp, const float4* __restrict__ ll,
    const float4* __restrict__ ww, float* __restrict__ out)
{
    __shared__ __align__(16) float sh[2 * NB];   // 32 KB: [tp NB][fp NB]
    const int task = blockIdx.y;
    const int t    = threadIdx.x;

    for (int i = t; i < 2 * NB; i += THREADS) sh[i] = 0.0f;
    __syncthreads();

    // ---- histogram phase: rotating 1-deep prefetch ----
    {
        const int start = blockIdx.x * PER_CHUNK;
        const int end   = (start + PER_CHUNK < N4) ? start + PER_CHUNK : N4;
        const int base  = task * N4 + start;
        const int cnt   = end - start;

        int i = t;
        float4 pv, lv, wv;
        if (i < cnt) {
            pv = __ldcs(pp + base + i);
            lv = __ldcs(ll + base + i);
            wv = __ldcs(ww + base + i);
        }
        while (i < cnt) {
            const int nxt = i + THREADS;
            float4 pv2, lv2, wv2;
            if (nxt < cnt) {                 // issue next loads BEFORE atomics
                pv2 = __ldcs(pp + base + nxt);
                lv2 = __ldcs(ll + base + nxt);
                wv2 = __ldcs(ww + base + nxt);
            }
#define DO_COMP(c)                                                        \
            {                                                             \
                int b = (int)(pv.c * (float)NB);                          \
                b = b > NB - 1 ? NB - 1 : b;                              \
                int off = b + ((lv.c == 0.0f) ? NB : 0);                  \
                atomicAdd(sh + off, wv.c);                                \
            }
            DO_COMP(x) DO_COMP(y) DO_COMP(z) DO_COMP(w)
#undef DO_COMP
            pv = pv2; lv = lv2; wv = wv2;
            i = nxt;
        }
    }
    __syncthreads();

    // ---- flush to global ----
    float* gh = g_hist + task * 2 * NB;
    for (int i = t; i < 2 * NB; i += THREADS) {
        float v = sh[i];
        if (v != 0.0f) atomicAdd(gh + i, v);
    }
    __threadfence();
    __syncthreads();

    // ---- elect last block per task ----
    __shared__ unsigned s_last;
    if (t == 0) s_last = atomicAdd(&g_count[task], 1u);
    __syncthreads();
    if (s_last != CHUNKS - 1) return;
    __threadfence();   // acquire: see all other blocks' hist atomics

    // ---- finalize (this block only): suffix scan + area + auc ----
    float* fsum = sh;                 // reuse smem (512 floats)
    float  th[BINS_PT], loc[BINS_PT];
    float  s = 0.0f;
#pragma unroll
    for (int j = BINS_PT - 1; j >= 0; --j) {
        th[j] = gh[t * BINS_PT + j];
        s += th[j];
        loc[j] = s;                   // inclusive suffix within thread's bins
    }
    __syncthreads();
    fsum[t] = s;
    __syncthreads();

    // Hillis-Steele inclusive suffix scan over 512 thread totals
    for (int off = 1; off < THREADS; off <<= 1) {
        float v = (t + off < THREADS) ? fsum[t + off] : 0.0f;
        __syncthreads();
        fsum[t] += v;
        __syncthreads();
    }
    const float above    = (t + 1 < THREADS) ? fsum[t + 1] : 0.0f;
    const float tp_total = fsum[0];
    __syncthreads();

    double a = 0.0, f = 0.0;
#pragma unroll
    for (int j = 0; j < BINS_PT; ++j) {
        float fv  = gh[NB + t * BINS_PT + j];
        float lut = above + loc[j] - 0.5f * th[j];
        a += (double)fv * (double)lut;
        f += (double)fv;
    }

#pragma unroll
    for (int off = 16; off; off >>= 1) {
        a += __shfl_down_sync(0xffffffffu, a, off);
        f += __shfl_down_sync(0xffffffffu, f, off);
    }
    double* sred = (double*)sh;       // reuse smem (32 doubles)
    const int warp = t >> 5, lane = t & 31;
    __syncthreads();
    if (lane == 0) { sred[warp] = a; sred[16 + warp] = f; }
    __syncthreads();

    if (t == 0) {
        double ta = 0.0, tf = 0.0;
#pragma unroll
        for (int k = 0; k < THREADS / 32; ++k) { ta += sred[k]; tf += sred[16 + k]; }
        double denom = tf * (double)tp_total;
        out[task] = (denom == 0.0) ? 0.5f : (float)(ta / denom);
        g_count[task] = 0u;           // restore invariant
    }

    // restore g_hist zeros for next call / replay
    for (int i = t; i < 2 * NB; i += THREADS) gh[i] = 0.0f;
}

extern "C" void kernel_launch(void* const* d_in, const int* in_sizes, int n_in,
                              void* d_out, int out_size) {
    int off = (n_in >= 4 && in_sizes[0] == 1) ? 1 : 0;
    const float4* p = (const float4*)d_in[off + 0];
    const float4* l = (const float4*)d_in[off + 1];
    const float4* w = (const float4*)d_in[off + 2];

    dim3 g(CHUNKS, T_TASKS);
    auc_kernel<<<g, THREADS>>>(p, l, w, (float*)d_out);
}